// round 8
// baseline (speedup 1.0000x reference)
#include <cuda_runtime.h>
#include <cstdint>

#define NATOMS_V 100
#define DIM    200
#define NPAD   256       // global col stride
#define CPAD   208       // computed cols (200 real + 8 pad)
#define LHID   6
#define LPRED  3
#define NADD   4
#define DPRED  204
#define NA     32
#define NTOT   8192
#define CK     16
#define NCH    13        // 12 x 16k + 1 x 8k

typedef unsigned long long ull;

// ---------- device scratch ----------
__device__ float g_act[2][NTOT][NPAD];
__device__ float g_wpad[9][DIM][NPAD];
__device__ float g_bpad[9][NPAD];

// ---------- helpers ----------
__device__ __forceinline__ void ffma2(ull& d, ull a, ull b) {
    asm("fma.rn.f32x2 %0, %1, %2, %0;" : "+l"(d) : "l"(a), "l"(b));
}
__device__ __forceinline__ ull dupf(float v) {
    float2 t = make_float2(v, v);
    return *(ull*)&t;
}
__device__ __forceinline__ uint32_t smaddr(const void* p) {
    return (uint32_t)__cvta_generic_to_shared(p);
}
__device__ __forceinline__ void cp_async16(uint32_t s, const void* g) {
    asm volatile("cp.async.cg.shared.global [%0], [%1], 16;" :: "r"(s), "l"(g));
}
__device__ __forceinline__ void cp_commit() { asm volatile("cp.async.commit_group;" ::: "memory"); }
__device__ __forceinline__ void cp_wait0()  { asm volatile("cp.async.wait_group 0;" ::: "memory"); }

struct LayerSmem {
    float  sA[2][NA][CK];       //  4.0 KB  A chunk ring
    float  sW[2][CK][CPAD];     // 26.6 KB  W chunk ring
    float  sHV[NA][CPAD];       // 26.6 KB  GEMM result for epilogue
    float2 sMd[NA][NA];         //  8.2 KB  message matrix (dup)
    float  sGam[NA];
    float  spv[2][DPRED + 4];
    float  sred[16];
};   // ~66.2 KB -> 2 CTAs/SM

// ---------- prep ----------
__global__ void prep_kernel(const float* __restrict__ Waw, const float* __restrict__ Wab,
                            const float* __restrict__ Wow, const float* __restrict__ Wob)
{
    const int stride = gridDim.x * blockDim.x;
    for (int idx = blockIdx.x * blockDim.x + threadIdx.x; idx < 9 * DIM * NPAD; idx += stride) {
        const int l = idx / (DIM * NPAD);
        const int rem = idx - l * DIM * NPAD;
        const int k = rem >> 8, c = rem & 255;
        float v = 0.f;
        if (c < DIM)
            v = (l < LHID) ? Waw[(l * DIM + k) * DIM + c]
                           : Wow[((l - LHID) * DIM + k) * DIM + c];
        g_wpad[l][k][c] = v;
    }
    for (int idx = blockIdx.x * blockDim.x + threadIdx.x; idx < 9 * NPAD; idx += stride) {
        const int l = idx >> 8, c = idx & 255;
        float v = 0.f;
        if (c < DIM)
            v = (l < LHID) ? Wab[l * DIM + c] : Wob[(l - LHID) * DIM + c];
        g_bpad[l][c] = v;
    }
}

// ---------- embed ----------
__global__ void embed_kernel(const int* __restrict__ atoms,
                             const float* __restrict__ embed_atom)
{
    int idx = blockIdx.x * blockDim.x + threadIdx.x;
    if (idx >= NTOT * DIM) return;
    const int row = idx / DIM, c = idx - row * DIM;
    g_act[0][row][c] = embed_atom[atoms[row] * DIM + c];
}

// ---------- layer kernel: 32x208 GEMM tile + fused epilogue ----------
// MODE 0: hidden (relu -> mix -> normalize -> g_act[pout])
// MODE 1: out layer (relu -> g_act[pout])
// MODE 2: final (relu -> molecule sum -> pred MLP -> out)
template<int MODE>
__global__ __launch_bounds__(512, 2)
void layer_kernel(int l, int pin, int pout,
                  const int*   __restrict__ atoms,
                  const float* __restrict__ dist,
                  const float* __restrict__ gamma_tab,
                  const float* __restrict__ adducts,
                  const float* __restrict__ W_pred_w,
                  const float* __restrict__ W_pred_b,
                  const float* __restrict__ W_prop_w,
                  const float* __restrict__ W_prop_b,
                  float* __restrict__ out)
{
    extern __shared__ char smraw[];
    LayerSmem& sm = *reinterpret_cast<LayerSmem*>(smraw);

    const int tid  = threadIdx.x;
    const int warp = tid >> 5, lane = tid & 31;
    const int row0 = blockIdx.x * NA;       // 1 molecule per CTA
    const int rg = warp >> 1, cg = warp & 1;
    const int r0 = rg * 4;                  // 4 rows per warp
    const int base = cg * 104;
    const int p0c = base + 2 * lane;                         // always valid (<208)
    const bool pv1 = (lane < 20);
    const int p1c = base + 64 + 2 * (pv1 ? lane : 0);        // clamped

    // stage chunk c into ring slot buf
    auto stage = [&](int c, int buf) {
        const int k0 = c * CK;
        const int cs = (c == NCH - 1) ? 8 : CK;
        const int nA = (NA * cs) / 4;             // 128 or 64 cp16
        if (tid < nA) {
            const int perRow = cs / 4;            // 4 or 2
            const int row = tid / perRow, q = (tid % perRow) * 4;
            cp_async16(smaddr(&sm.sA[buf][row][q]), &g_act[pin][row0 + row][k0 + q]);
        }
        const int nW = cs * 52;                   // 832 or 416 cp16
        for (int o = tid; o < nW; o += 512) {
            const int kr = o / 52, c4 = (o - kr * 52) * 4;
            cp_async16(smaddr(&sm.sW[buf][kr][c4]), &g_wpad[l][k0 + kr][c4]);
        }
    };

    stage(0, 0);
    cp_commit();

    if (MODE == 0) {   // message-matrix prep overlaps stage 0
        if (tid < NA) sm.sGam[tid] = gamma_tab[l * NATOMS_V + atoms[row0 + tid]];
        __syncthreads();
        #pragma unroll
        for (int i = 0; i < 2; i++) {
            const int idx = tid + i * 512;
            const int ii = idx >> 5, jj = idx & 31;
            const float d = dist[(row0 + ii) * NTOT + row0 + jj];
            const float e = __expf(-sm.sGam[jj] * d * d);
            sm.sMd[ii][jj] = make_float2(e, e);
        }
    }

    ull acc[4][2];
    #pragma unroll
    for (int r = 0; r < 4; r++) { acc[r][0] = 0ull; acc[r][1] = 0ull; }

    for (int c = 0; c < NCH; c++) {
        cp_wait0();
        __syncthreads();
        if (c + 1 < NCH) stage(c + 1, (c + 1) & 1);
        cp_commit();
        const int buf = c & 1;
        const int cs = (c == NCH - 1) ? 8 : CK;
        for (int kk = 0; kk < cs; kk += 4) {
            float4 a4[4];
            #pragma unroll
            for (int r = 0; r < 4; r++)
                a4[r] = *(const float4*)&sm.sA[buf][r0 + r][kk];   // broadcast LDS.128
            #pragma unroll
            for (int q = 0; q < 4; q++) {
                const ull w0 = *(const ull*)&sm.sW[buf][kk + q][p0c];
                const ull w1 = *(const ull*)&sm.sW[buf][kk + q][p1c];
                #pragma unroll
                for (int r = 0; r < 4; r++) {
                    const ull a = dupf(((const float*)&a4[r])[q]);
                    ffma2(acc[r][0], a, w0);
                    ffma2(acc[r][1], a, w1);
                }
            }
        }
    }

    const float2 b0 = *(const float2*)&g_bpad[l][p0c];
    const float2 b1 = *(const float2*)&g_bpad[l][p1c];

    if (MODE == 1) {
        #pragma unroll
        for (int r = 0; r < 4; r++) {
            const int grow = row0 + r0 + r;
            float2 v = *(float2*)&acc[r][0];
            *(float2*)&g_act[pout][grow][p0c] =
                make_float2(fmaxf(v.x + b0.x, 0.f), fmaxf(v.y + b0.y, 0.f));
            if (pv1) {
                float2 u = *(float2*)&acc[r][1];
                *(float2*)&g_act[pout][grow][p1c] =
                    make_float2(fmaxf(u.x + b1.x, 0.f), fmaxf(u.y + b1.y, 0.f));
            }
        }
        return;
    }

    // MODE 0 / 2: hv to smem
    #pragma unroll
    for (int r = 0; r < 4; r++) {
        float2 v = *(float2*)&acc[r][0];
        *(float2*)&sm.sHV[r0 + r][p0c] =
            make_float2(fmaxf(v.x + b0.x, 0.f), fmaxf(v.y + b0.y, 0.f));
        if (pv1) {
            float2 u = *(float2*)&acc[r][1];
            *(float2*)&sm.sHV[r0 + r][p1c] =
                make_float2(fmaxf(u.x + b1.x, 0.f), fmaxf(u.y + b1.y, 0.f));
        }
    }
    __syncthreads();

    if (MODE == 0) {
        // mix + normalize: warp -> 2 rows, full 200 cols
        const int i0 = warp * 2;
        const bool has3 = (lane < 4);
        const int m0 = 2 * lane, m1 = m0 + 64, m2 = m0 + 128, m3 = 192 + 2 * lane;

        ull a2[2][4];
        #pragma unroll
        for (int r = 0; r < 2; r++) {
            a2[r][0] = *(const ull*)&sm.sHV[i0 + r][m0];
            a2[r][1] = *(const ull*)&sm.sHV[i0 + r][m1];
            a2[r][2] = *(const ull*)&sm.sHV[i0 + r][m2];
            a2[r][3] = has3 ? *(const ull*)&sm.sHV[i0 + r][m3] : 0ull;
        }
        #pragma unroll 4
        for (int j = 0; j < NA; j++) {
            ull mm0 = *(const ull*)&sm.sMd[i0][j];
            ull mm1 = *(const ull*)&sm.sMd[i0 + 1][j];
            ull h0 = *(const ull*)&sm.sHV[j][m0];
            ull h1 = *(const ull*)&sm.sHV[j][m1];
            ull h2 = *(const ull*)&sm.sHV[j][m2];
            ffma2(a2[0][0], mm0, h0); ffma2(a2[1][0], mm1, h0);
            ffma2(a2[0][1], mm0, h1); ffma2(a2[1][1], mm1, h1);
            ffma2(a2[0][2], mm0, h2); ffma2(a2[1][2], mm1, h2);
            if (has3) {
                ull h3 = *(const ull*)&sm.sHV[j][m3];
                ffma2(a2[0][3], mm0, h3); ffma2(a2[1][3], mm1, h3);
            }
        }
        #pragma unroll
        for (int r = 0; r < 2; r++) {
            float ss = 0.f;
            #pragma unroll
            for (int u = 0; u < 4; u++) {
                float2 v = *(float2*)&a2[r][u];
                ss += v.x * v.x + v.y * v.y;
            }
            #pragma unroll
            for (int o = 16; o > 0; o >>= 1)
                ss += __shfl_xor_sync(0xffffffffu, ss, o);
            const float scale = 1.f / fmaxf(sqrtf(ss), 1e-12f);
            const int grow = row0 + i0 + r;
            #pragma unroll
            for (int u = 0; u < 3; u++) {
                float2 v = *(float2*)&a2[r][u];
                *(float2*)&g_act[pout][grow][m0 + 64 * u] =
                    make_float2(v.x * scale, v.y * scale);
            }
            if (has3) {
                float2 v = *(float2*)&a2[r][3];
                *(float2*)&g_act[pout][grow][m3] =
                    make_float2(v.x * scale, v.y * scale);
            }
        }
        return;
    }

    // MODE 2: molecule sum + adducts + pred MLP + final dot
    {
        if (tid < DPRED) {
            float s;
            if (tid < DIM) {
                s = 0.f;
                #pragma unroll 8
                for (int i = 0; i < NA; i++) s += sm.sHV[i][tid];
            } else {
                s = adducts[blockIdx.x * NADD + (tid - DIM)];
            }
            sm.spv[0][tid] = s;
        }
        __syncthreads();

        int cur = 0;
        for (int lp = 0; lp < LPRED; lp++) {
            if (tid < DPRED) {
                const float* Wp = W_pred_w + lp * DPRED * DPRED;
                float a = W_pred_b[lp * DPRED + tid];
                #pragma unroll 4
                for (int k = 0; k < DPRED; k++)
                    a += sm.spv[cur][k] * Wp[k * DPRED + tid];
                sm.spv[cur ^ 1][tid] = fmaxf(a, 0.f);
            }
            __syncthreads();
            cur ^= 1;
        }

        float p = (tid < DPRED) ? sm.spv[cur][tid] * W_prop_w[tid] : 0.f;
        #pragma unroll
        for (int o = 16; o > 0; o >>= 1)
            p += __shfl_xor_sync(0xffffffffu, p, o);
        if (lane == 0) sm.sred[warp] = p;
        __syncthreads();
        if (tid == 0) {
            float s = 0.f;
            #pragma unroll
            for (int w = 0; w < 16; w++) s += sm.sred[w];
            out[blockIdx.x] = s + W_prop_b[0];
        }
    }
}

// ---------- launch ----------
extern "C" void kernel_launch(void* const* d_in, const int* in_sizes, int n_in,
                              void* d_out, int out_size)
{
    const int*   atoms      = (const int*)  d_in[0];
    const float* dist       = (const float*)d_in[1];
    const float* adducts    = (const float*)d_in[2];
    const float* embed_atom = (const float*)d_in[3];
    const float* gamma_tab  = (const float*)d_in[4];
    const float* W_atom_w   = (const float*)d_in[5];
    const float* W_atom_b   = (const float*)d_in[6];
    const float* W_out_w    = (const float*)d_in[7];
    const float* W_out_b    = (const float*)d_in[8];
    const float* W_pred_w   = (const float*)d_in[9];
    const float* W_pred_b   = (const float*)d_in[10];
    const float* W_prop_w   = (const float*)d_in[11];
    const float* W_prop_b   = (const float*)d_in[12];
    float* out = (float*)d_out;

    const int smem = (int)sizeof(LayerSmem);
    cudaFuncSetAttribute(layer_kernel<0>, cudaFuncAttributeMaxDynamicSharedMemorySize, smem);
    cudaFuncSetAttribute(layer_kernel<1>, cudaFuncAttributeMaxDynamicSharedMemorySize, smem);
    cudaFuncSetAttribute(layer_kernel<2>, cudaFuncAttributeMaxDynamicSharedMemorySize, smem);

    prep_kernel<<<512, 256>>>(W_atom_w, W_atom_b, W_out_w, W_out_b);
    embed_kernel<<<(NTOT * DIM + 511) / 512, 512>>>(atoms, embed_atom);

    for (int l = 0; l < LHID; l++)
        layer_kernel<0><<<256, 512, smem>>>(l, l & 1, (l & 1) ^ 1,
            atoms, dist, gamma_tab, adducts, W_pred_w, W_pred_b, W_prop_w, W_prop_b, out);

    layer_kernel<1><<<256, 512, smem>>>(6, 0, 1,
        atoms, dist, gamma_tab, adducts, W_pred_w, W_pred_b, W_prop_w, W_prop_b, out);
    layer_kernel<1><<<256, 512, smem>>>(7, 1, 0,
        atoms, dist, gamma_tab, adducts, W_pred_w, W_pred_b, W_prop_w, W_prop_b, out);
    layer_kernel<2><<<256, 512, smem>>>(8, 0, 0,
        atoms, dist, gamma_tab, adducts, W_pred_w, W_pred_b, W_prop_w, W_prop_b, out);
}